// round 1
// baseline (speedup 1.0000x reference)
#include <cuda_runtime.h>
#include <math_constants.h>

#define BSZ      1024
#define KCOLS    66560          // BSZ + 65536
#define KV4      (KCOLS / 4)    // 16640 float4 per row
#define NTHREADS 256
#define NWARPS   (NTHREADS / 32)
#define CAP      4096           // candidate buffer slots (expected ~400 used)
#define TCAND    2.5f           // capture threshold on raw logit

__device__ float g_row_loss[BSZ];

__global__ __launch_bounds__(NTHREADS) void wl_row_kernel(const float* __restrict__ logits)
{
    const int row = blockIdx.x;
    const float4* __restrict__ rp =
        reinterpret_cast<const float4*>(logits + (size_t)row * KCOLS);

    __shared__ float s_cand[CAP];
    __shared__ int   s_cnt;
    __shared__ float s_sum[NWARPS];
    __shared__ float s_max[NWARPS];
    __shared__ float s_par[4];  // inv, m, dl, fast-flag

    const int tid = threadIdx.x;
    if (tid == 0) s_cnt = 0;
    __syncthreads();

    const int diag_v = row >> 2;   // float4 index containing the diagonal
    const int diag_c = row & 3;    // component within it

    // ---------------- Pass 1: sum(exp(l)), off-diag max(l), candidate capture ----
    float sum = 0.f;
    float mxo = -CUDART_INF_F;     // max over OFF-DIAGONAL logits only

    #pragma unroll 4
    for (int v = tid; v < KV4; v += NTHREADS) {
        float4 x = rp[v];
        sum += (__expf(x.x) + __expf(x.y)) + (__expf(x.z) + __expf(x.w));
        if (v != diag_v) {
            mxo = fmaxf(mxo, fmaxf(fmaxf(x.x, x.y), fmaxf(x.z, x.w)));
            if (x.x >= TCAND) { int p = atomicAdd(&s_cnt, 1); if (p < CAP) s_cand[p] = x.x; }
            if (x.y >= TCAND) { int p = atomicAdd(&s_cnt, 1); if (p < CAP) s_cand[p] = x.y; }
            if (x.z >= TCAND) { int p = atomicAdd(&s_cnt, 1); if (p < CAP) s_cand[p] = x.z; }
            if (x.w >= TCAND) { int p = atomicAdd(&s_cnt, 1); if (p < CAP) s_cand[p] = x.w; }
        } else {
            float c[4] = {x.x, x.y, x.z, x.w};
            #pragma unroll
            for (int q = 0; q < 4; q++) {
                if (q != diag_c) {
                    mxo = fmaxf(mxo, c[q]);
                    if (c[q] >= TCAND) { int p = atomicAdd(&s_cnt, 1); if (p < CAP) s_cand[p] = c[q]; }
                }
            }
        }
    }

    #pragma unroll
    for (int o = 16; o; o >>= 1) {
        sum += __shfl_xor_sync(0xffffffffu, sum, o);
        mxo  = fmaxf(mxo, __shfl_xor_sync(0xffffffffu, mxo, o));
    }
    if ((tid & 31) == 0) { s_sum[tid >> 5] = sum; s_max[tid >> 5] = mxo; }
    __syncthreads();

    if (tid == 0) {
        float S = 0.f, M = -CUDART_INF_F;
        #pragma unroll
        for (int i = 0; i < NWARPS; i++) { S += s_sum[i]; M = fmaxf(M, s_max[i]); }
        float dl       = logits[(size_t)row * KCOLS + row];           // L1/L2 hit
        float neg_mean = (S - __expf(dl)) * (1.0f / (float)(KCOLS - 1));
        float inv      = 1.0f / neg_mean;
        // g(l) = l*exp(l)*inv is monotone for l >= -1; M >= TCAND > 0 in fast path,
        // so g(M) is the EXACT off-diagonal max of u. True row max m = max(g(M), dl).
        float gmo = M * __expf(M) * inv;
        float m   = fmaxf(gmo, dl);
        float gT  = TCAND * __expf(TCAND) * inv;   // upper bound on u of any non-candidate
        // fast path: candidates provably contain everything non-negligible
        bool fast = (M >= TCAND) && (neg_mean > 0.f) &&
                    (gT <= m - 30.f) && (s_cnt <= CAP);
        s_par[0] = inv; s_par[1] = m; s_par[2] = dl; s_par[3] = fast ? 1.f : 0.f;
    }
    __syncthreads();

    const float inv = s_par[0], m = s_par[1], dl = s_par[2];
    const bool  fast = (s_par[3] != 0.f);

    if (fast) {
        // ---------------- Pass 2 (fast): only captured candidates, no memory re-read
        const int nc = s_cnt;   // <= CAP guaranteed by fast flag
        float sl = 0.f;
        for (int i = tid; i < nc; i += NTHREADS) {
            float l = s_cand[i];
            float u = l * __expf(l) * inv;
            sl += __expf(u - m);
        }
        #pragma unroll
        for (int o = 16; o; o >>= 1) sl += __shfl_xor_sync(0xffffffffu, sl, o);
        if ((tid & 31) == 0) s_sum[tid >> 5] = sl;
        __syncthreads();
        if (tid == 0) {
            float s = __expf(dl - m);           // diagonal term (u_ii = dl, unscaled)
            #pragma unroll
            for (int i = 0; i < NWARPS; i++) s += s_sum[i];
            g_row_loss[row] = m + logf(s) - dl;
        }
    } else {
        // ---------------- Pass 2 (robust fallback): full online LSE re-read --------
        float mt = -CUDART_INF_F, st = 0.f;
        for (int v = tid; v < KV4; v += NTHREADS) {
            float4 x = rp[v];
            float c[4] = {x.x, x.y, x.z, x.w};
            #pragma unroll
            for (int q = 0; q < 4; q++) {
                int   j = v * 4 + q;
                float u = (j == row) ? dl : c[q] * __expf(c[q]) * inv;
                float nm = fmaxf(mt, u);
                st = st * __expf(mt - nm) + __expf(u - nm);
                mt = nm;
            }
        }
        #pragma unroll
        for (int o = 16; o; o >>= 1) {
            float om = __shfl_xor_sync(0xffffffffu, mt, o);
            float os = __shfl_xor_sync(0xffffffffu, st, o);
            float nm = fmaxf(mt, om);
            st = st * __expf(mt - nm) + os * __expf(om - nm);
            mt = nm;
        }
        if ((tid & 31) == 0) { s_sum[tid >> 5] = st; s_max[tid >> 5] = mt; }
        __syncthreads();
        if (tid == 0) {
            float m2 = -CUDART_INF_F, s2 = 0.f;
            #pragma unroll
            for (int i = 0; i < NWARPS; i++) m2 = fmaxf(m2, s_max[i]);
            #pragma unroll
            for (int i = 0; i < NWARPS; i++) s2 += s_sum[i] * __expf(s_max[i] - m2);
            g_row_loss[row] = m2 + logf(s2) - dl;
        }
    }
}

__global__ __launch_bounds__(1024) void wl_reduce_kernel(float* __restrict__ out)
{
    __shared__ float sh[32];
    const int tid = threadIdx.x;
    float v = g_row_loss[tid];
    #pragma unroll
    for (int o = 16; o; o >>= 1) v += __shfl_xor_sync(0xffffffffu, v, o);
    if ((tid & 31) == 0) sh[tid >> 5] = v;
    __syncthreads();
    if (tid < 32) {
        float t = sh[tid];
        #pragma unroll
        for (int o = 16; o; o >>= 1) t += __shfl_xor_sync(0xffffffffu, t, o);
        if (tid == 0) out[0] = t * (1.0f / (float)BSZ);
    }
}

extern "C" void kernel_launch(void* const* d_in, const int* in_sizes, int n_in,
                              void* d_out, int out_size)
{
    const float* logits = (const float*)d_in[0];
    (void)in_sizes; (void)n_in; (void)out_size;
    wl_row_kernel<<<BSZ, NTHREADS>>>(logits);
    wl_reduce_kernel<<<1, 1024>>>((float*)d_out);
}